// round 9
// baseline (speedup 1.0000x reference)
#include <cuda_runtime.h>
#include <cuda_fp16.h>
#include <math_constants.h>

#define N_NODES   100000
#define N_EDGES   1200000
#define NGRAPHS   128

// ---------------- scratch (device globals: allocation-free) ----------------
__device__ float  g_Q[N_NODES * 64];
__device__ float  g_QE[N_NODES * 64];
__device__ __half g_KV[N_NODES * 128];   // K halves [0,64), V halves [64,128)
__device__ float  g_S[N_NODES * 64];
__device__ float  g_H0[N_NODES * 64];
__device__ float  g_H1[N_NODES * 64];
__device__ __half g_pattr[(size_t)N_EDGES * 16];  // edge_attr, CSR order, fp16
__device__ int    g_cnt[N_NODES];        // zeroed at load; re-zeroed by k_cleanup
__device__ int    g_rowptr[N_NODES + 1];
__device__ int    g_cursor[N_NODES];
__device__ int    g_psrc[N_EDGES];
__device__ float  g_pool[NGRAPHS * 64];
__device__ float  g_gcnt[NGRAPHS];

__device__ __forceinline__ float ex2(float x) {
    float y;
    asm("ex2.approx.ftz.f32 %0, %1;" : "=f"(y) : "f"(x));
    return y;
}
__device__ __forceinline__ void ldsm_x4(unsigned* r, unsigned addr) {
    asm volatile("ldmatrix.sync.aligned.m8n8.x4.shared.b16 {%0,%1,%2,%3}, [%4];"
                 : "=r"(r[0]), "=r"(r[1]), "=r"(r[2]), "=r"(r[3]) : "r"(addr));
}
__device__ __forceinline__ void ldsm_x2t(unsigned* r, unsigned addr) {
    asm volatile("ldmatrix.sync.aligned.m8n8.x2.trans.shared.b16 {%0,%1}, [%2];"
                 : "=r"(r[0]), "=r"(r[1]) : "r"(addr));
}
__device__ __forceinline__ void mma16816(float* c, const unsigned* a, const unsigned* b) {
    asm volatile("mma.sync.aligned.m16n8k16.row.col.f32.f16.f16.f32 "
                 "{%0,%1,%2,%3}, {%4,%5,%6,%7}, {%8,%9}, {%0,%1,%2,%3};"
                 : "+f"(c[0]), "+f"(c[1]), "+f"(c[2]), "+f"(c[3])
                 : "r"(a[0]), "r"(a[1]), "r"(a[2]), "r"(a[3]), "r"(b[0]), "r"(b[1]));
}
// hi/lo split: v = hi + lo to ~2^-22
__device__ __forceinline__ void split2(float2 v, __half2& hi, __half2& lo) {
    hi = __float22half2_rn(v);
    float2 h = __half22float2(hi);
    lo = __float22half2_rn(make_float2(v.x - h.x, v.y - h.y));
}
// 8 packed halves -> 8 floats
__device__ __forceinline__ void cvt8(const uint4& r, float* f) {
    float2 a = __half22float2(*(const __half2*)&r.x);
    float2 b = __half22float2(*(const __half2*)&r.y);
    float2 c = __half22float2(*(const __half2*)&r.z);
    float2 d = __half22float2(*(const __half2*)&r.w);
    f[0] = a.x; f[1] = a.y; f[2] = b.x; f[3] = b.y;
    f[4] = c.x; f[5] = c.y; f[6] = d.x; f[7] = d.y;
}

// ---------------- CSR build ----------------
__global__ void k_hist(const int* __restrict__ ei) {
    int e = blockIdx.x * blockDim.x + threadIdx.x;
    if (e < N_EDGES) {
        int d = ei[N_EDGES + e];
        if (d >= 0 && d < N_NODES) atomicAdd(&g_cnt[d], 1);
    }
}

__global__ void k_scan() {
    __shared__ int part[1024];
    const int CH = 98;
    int t = threadIdx.x;
    int beg = t * CH;
    int end = beg + CH; if (end > N_NODES) end = N_NODES;
    int s = 0;
    for (int i = beg; i < end; i++) s += g_cnt[i];
    part[t] = s;
    __syncthreads();
    for (int off = 1; off < 1024; off <<= 1) {
        int v = (t >= off) ? part[t - off] : 0;
        __syncthreads();
        part[t] += v;
        __syncthreads();
    }
    int run = (t > 0) ? part[t - 1] : 0;
    for (int i = beg; i < end; i++) {
        g_rowptr[i] = run;
        g_cursor[i] = run;
        run += g_cnt[i];
    }
    if (t == 0) g_rowptr[N_NODES] = part[1023];
}

// scatter src + convert/permute edge_attr to fp16 CSR order, in one pass
__global__ void k_scatter(const int* __restrict__ ei, const float* __restrict__ eattr) {
    int e = blockIdx.x * blockDim.x + threadIdx.x;
    if (e < N_EDGES) {
        int d = ei[N_EDGES + e];
        if (d >= 0 && d < N_NODES) {
            int p = atomicAdd(&g_cursor[d], 1);
            g_psrc[p] = ei[e];
            const float4* ap = (const float4*)(eattr + (size_t)e * 16);
            float4 a0 = __ldg(ap + 0), a1 = __ldg(ap + 1);
            float4 a2 = __ldg(ap + 2), a3 = __ldg(ap + 3);
            __half2 h[8];
            h[0] = __float22half2_rn(make_float2(a0.x, a0.y));
            h[1] = __float22half2_rn(make_float2(a0.z, a0.w));
            h[2] = __float22half2_rn(make_float2(a1.x, a1.y));
            h[3] = __float22half2_rn(make_float2(a1.z, a1.w));
            h[4] = __float22half2_rn(make_float2(a2.x, a2.y));
            h[5] = __float22half2_rn(make_float2(a2.z, a2.w));
            h[6] = __float22half2_rn(make_float2(a3.x, a3.y));
            h[7] = __float22half2_rn(make_float2(a3.z, a3.w));
            uint4* dst = (uint4*)(g_pattr + (size_t)p * 16);
            dst[0] = *(uint4*)&h[0];
            dst[1] = *(uint4*)&h[4];
        }
    }
}

// ---------------- QKVS GEMM via split-fp16 HMMA (Markidis 3-term) ----------
#define XST 72
__global__ void __launch_bounds__(128)
k_qkvs(int insel, const float* __restrict__ Xext,
       const float* __restrict__ Wq, const float* __restrict__ Wk,
       const float* __restrict__ Wv, const float* __restrict__ Ws,
       const float* __restrict__ bq, const float* __restrict__ bk,
       const float* __restrict__ bv, const float* __restrict__ bs) {
    __shared__ __half Xhi[64 * XST], Xlo[64 * XST];
    __shared__ __half Whi[64 * XST], Wlo[64 * XST];

    const float* X = (insel == 0) ? Xext : (insel == 1) ? g_H0 : g_H1;
    int mat = blockIdx.y;
    const float* W = (mat == 0) ? Wq : (mat == 1) ? Wk : (mat == 2) ? Wv : Ws;
    const float* b = (mat == 0) ? bq : (mat == 1) ? bk : (mat == 2) ? bv : bs;

    int tid = threadIdx.x;
    int warp = tid >> 5, lane = tid & 31;
    int rowBase = blockIdx.x * 64;

    for (int i = tid; i < 1024; i += 128) {
        int r = i >> 4, c4 = (i & 15) * 4;
        int row = rowBase + r;
        float4 v = (row < N_NODES) ? *(const float4*)(X + (size_t)row * 64 + c4)
                                   : make_float4(0.f, 0.f, 0.f, 0.f);
        __half2 hi, lo;
        split2(make_float2(v.x, v.y), hi, lo);
        *(__half2*)(Xhi + r * XST + c4) = hi;
        *(__half2*)(Xlo + r * XST + c4) = lo;
        split2(make_float2(v.z, v.w), hi, lo);
        *(__half2*)(Xhi + r * XST + c4 + 2) = hi;
        *(__half2*)(Xlo + r * XST + c4 + 2) = lo;

        float4 w = *(const float4*)(W + r * 64 + c4);
        split2(make_float2(w.x, w.y), hi, lo);
        *(__half2*)(Whi + r * XST + c4) = hi;
        *(__half2*)(Wlo + r * XST + c4) = lo;
        split2(make_float2(w.z, w.w), hi, lo);
        *(__half2*)(Whi + r * XST + c4 + 2) = hi;
        *(__half2*)(Wlo + r * XST + c4 + 2) = lo;
    }
    __syncthreads();

    unsigned xhi_a = (unsigned)__cvta_generic_to_shared(Xhi);
    unsigned xlo_a = (unsigned)__cvta_generic_to_shared(Xlo);
    unsigned whi_a = (unsigned)__cvta_generic_to_shared(Whi);
    unsigned wlo_a = (unsigned)__cvta_generic_to_shared(Wlo);
    int warpRow = warp * 16;
    int lr = lane & 15, lh = lane >> 4;

    float acc[8][4];
#pragma unroll
    for (int nb = 0; nb < 8; nb++)
#pragma unroll
        for (int j = 0; j < 4; j++) acc[nb][j] = 0.f;

#pragma unroll
    for (int ks = 0; ks < 4; ks++) {
        unsigned ahi[4], alo[4];
        unsigned aoff = ((warpRow + lr) * XST + ks * 16 + lh * 8) * 2;
        ldsm_x4(ahi, xhi_a + aoff);
        ldsm_x4(alo, xlo_a + aoff);
#pragma unroll
        for (int nb = 0; nb < 8; nb++) {
            unsigned bhi[2], blo[2];
            unsigned boff = ((ks * 16 + lr) * XST + nb * 8) * 2;
            ldsm_x2t(bhi, whi_a + boff);
            ldsm_x2t(blo, wlo_a + boff);
            mma16816(acc[nb], ahi, bhi);
            mma16816(acc[nb], ahi, blo);
            mma16816(acc[nb], alo, bhi);
        }
    }

    int r0 = rowBase + warpRow + (lane >> 2);
    int cb = 2 * (lane & 3);
    if (mat == 0 || mat == 3) {
        float* out = (mat == 0) ? g_Q : g_S;
#pragma unroll
        for (int nb = 0; nb < 8; nb++) {
            int col = nb * 8 + cb;
            float2 bv = *(const float2*)(b + col);
            if (r0 < N_NODES)
                *(float2*)(out + (size_t)r0 * 64 + col) =
                    make_float2(acc[nb][0] + bv.x, acc[nb][1] + bv.y);
            if (r0 + 8 < N_NODES)
                *(float2*)(out + (size_t)(r0 + 8) * 64 + col) =
                    make_float2(acc[nb][2] + bv.x, acc[nb][3] + bv.y);
        }
    } else {
        int off = (mat == 1) ? 0 : 64;
#pragma unroll
        for (int nb = 0; nb < 8; nb++) {
            int col = nb * 8 + cb;
            float2 bv = *(const float2*)(b + col);
            if (r0 < N_NODES)
                *(__half2*)(g_KV + (size_t)r0 * 128 + off + col) =
                    __float22half2_rn(make_float2(acc[nb][0] + bv.x, acc[nb][1] + bv.y));
            if (r0 + 8 < N_NODES)
                *(__half2*)(g_KV + (size_t)(r0 + 8) * 128 + off + col) =
                    __float22half2_rn(make_float2(acc[nb][2] + bv.x, acc[nb][3] + bv.y));
        }
    }
}

// ---------------- qe precompute: qe[n,h*16+j] = QS * sum_d Q[n,h,d]*We[j,h,d]
__global__ void k_qe(const float* __restrict__ We_l) {
    __shared__ float Wsm[16 * 68];
    int tid = threadIdx.x;
    for (int i = tid; i < 1024; i += 256)
        Wsm[(i >> 6) * 68 + (i & 63)] = We_l[i];
    __syncthreads();
    const float QS = 0.25f * 1.4426950408889634f;   // 1/sqrt(16) * log2(e)
    int idx = blockIdx.x * 256 + tid;
    if (idx < N_NODES * 64) {
        int n = idx >> 6, p = idx & 63;
        int h = p >> 4, j = p & 15;
        const float* qrow = g_Q + n * 64 + h * 16;
        const float* wrow = Wsm + j * 68 + h * 16;
        float s = 0.f;
#pragma unroll
        for (int d = 0; d < 16; d++) s = fmaf(qrow[d], wrow[d], s);
        g_QE[idx] = s * QS;
    }
}

// ---------------- edge attention: quarter-warp per edge, 8 ch/lane --------
// lane = 8*quarter + sub.  Lane owns channels [8*sub, 8*sub+8) (head sub/2)
// and attr indices [8*(sub&1), 8*(sub&1)+8).  Each quarter runs an
// independent online softmax over edges beg+quarter, +4, ... ; the four
// partial states are merged once per node via xor-butterfly.
__global__ void __launch_bounds__(256) k_edge(const float* __restrict__ We_l,
                                              const float* __restrict__ be_l,
                                              int outsel, int do_relu) {
    __shared__ float sWe[1024];
    float* Hout = (outsel == 0) ? g_H0 : g_H1;
    int tid = threadIdx.x;
    for (int i = tid; i < 1024; i += 256) sWe[i] = We_l[i];
    __syncthreads();

    int lane = tid & 31;
    int sub = lane & 7, quarter = lane >> 3;
    int coff = sub * 8;             // this lane's 8 channels
    int jown = 8 * (sub & 1);       // this lane's attr base index
    const float QS = 0.25f * 1.4426950408889634f;

    int gw = (blockIdx.x * 256 + tid) >> 5;
    int nw = (gridDim.x * 256) >> 5;

    for (int n = gw; n < N_NODES; n += nw) {
        int beg = g_rowptr[n], end = g_rowptr[n + 1];
        int deg = end - beg;

        float q8[8], qe8[8];
        {
            float4 a = *(const float4*)(g_Q + (size_t)n * 64 + coff);
            float4 b = *(const float4*)(g_Q + (size_t)n * 64 + coff + 4);
            q8[0] = a.x * QS; q8[1] = a.y * QS; q8[2] = a.z * QS; q8[3] = a.w * QS;
            q8[4] = b.x * QS; q8[5] = b.y * QS; q8[6] = b.z * QS; q8[7] = b.w * QS;
            float4 c = *(const float4*)(g_QE + (size_t)n * 64 + coff);
            float4 e2 = *(const float4*)(g_QE + (size_t)n * 64 + coff + 4);
            qe8[0] = c.x; qe8[1] = c.y; qe8[2] = c.z; qe8[3] = c.w;
            qe8[4] = e2.x; qe8[5] = e2.y; qe8[6] = e2.z; qe8[7] = e2.w;
        }

        float m = -CUDART_INF_F, d = 0.f;
        float acc[8], t[8];
#pragma unroll
        for (int j = 0; j < 8; j++) { acc[j] = 0.f; t[j] = 0.f; }

        int trips = (deg + 3) >> 2;
        for (int i = 0; i < trips; i++) {
            int e = beg + quarter + i * 4;
            bool valid = (e < end);
            int ec = valid ? e : (end - 1);
            int s = g_psrc[ec];
            uint4 kr = *(const uint4*)(g_KV + (size_t)s * 128 + coff);
            uint4 vr = *(const uint4*)(g_KV + (size_t)s * 128 + 64 + coff);
            uint4 ar = *(const uint4*)(g_pattr + (size_t)ec * 16 + jown);
            float k8[8], v8[8], a8[8];
            cvt8(kr, k8); cvt8(vr, v8); cvt8(ar, a8);

            float lp = 0.f;
#pragma unroll
            for (int j = 0; j < 8; j++) lp = fmaf(q8[j], k8[j], lp);
#pragma unroll
            for (int j = 0; j < 8; j++) lp = fmaf(qe8[j], a8[j], lp);
            lp += __shfl_xor_sync(0xffffffffu, lp, 1);   // full head logit*log2e

            if (valid) {
                float nm = fmaxf(m, lp);
                float p  = ex2(lp - nm);
                float sc = ex2(m - nm);
                d = fmaf(d, sc, p);
#pragma unroll
                for (int j = 0; j < 8; j++) acc[j] = fmaf(acc[j], sc, p * v8[j]);
#pragma unroll
                for (int j = 0; j < 8; j++) t[j] = fmaf(t[j], sc, p * a8[j]);
                m = nm;
            }
        }

        // merge the 4 quarter-states (online-softmax combine, xor butterfly)
#pragma unroll
        for (int off = 8; off <= 16; off <<= 1) {
            float m2 = __shfl_xor_sync(0xffffffffu, m, off);
            float d2 = __shfl_xor_sync(0xffffffffu, d, off);
            float nm = fmaxf(m, m2);
            float s1, s2;
            if (nm == -CUDART_INF_F) { s1 = 0.f; s2 = 0.f; }
            else { s1 = ex2(m - nm); s2 = ex2(m2 - nm); }
            d = d * s1 + d2 * s2;
#pragma unroll
            for (int j = 0; j < 8; j++) {
                float a2 = __shfl_xor_sync(0xffffffffu, acc[j], off);
                acc[j] = acc[j] * s1 + a2 * s2;
                float t2 = __shfl_xor_sync(0xffffffffu, t[j], off);
                t[j] = t[j] * s1 + t2 * s2;
            }
            m = nm;
        }

        // ws = We^T t for this lane's 8 channels (t split across the lane pair)
        float ws[8];
#pragma unroll
        for (int j = 0; j < 8; j++) ws[j] = 0.f;
#pragma unroll
        for (int j2 = 0; j2 < 8; j2++) {
            float tp = __shfl_xor_sync(0xffffffffu, t[j2], 1);
            const float* w0 = sWe + (jown + j2) * 64 + coff;
            const float* w1 = sWe + (8 - jown + j2) * 64 + coff;
            float4 w0a = *(const float4*)w0, w0b = *(const float4*)(w0 + 4);
            float4 w1a = *(const float4*)w1, w1b = *(const float4*)(w1 + 4);
            ws[0] = fmaf(w0a.x, t[j2], ws[0]); ws[1] = fmaf(w0a.y, t[j2], ws[1]);
            ws[2] = fmaf(w0a.z, t[j2], ws[2]); ws[3] = fmaf(w0a.w, t[j2], ws[3]);
            ws[4] = fmaf(w0b.x, t[j2], ws[4]); ws[5] = fmaf(w0b.y, t[j2], ws[5]);
            ws[6] = fmaf(w0b.z, t[j2], ws[6]); ws[7] = fmaf(w0b.w, t[j2], ws[7]);
            ws[0] = fmaf(w1a.x, tp, ws[0]); ws[1] = fmaf(w1a.y, tp, ws[1]);
            ws[2] = fmaf(w1a.z, tp, ws[2]); ws[3] = fmaf(w1a.w, tp, ws[3]);
            ws[4] = fmaf(w1b.x, tp, ws[4]); ws[5] = fmaf(w1b.y, tp, ws[5]);
            ws[6] = fmaf(w1b.z, tp, ws[6]); ws[7] = fmaf(w1b.w, tp, ws[7]);
        }

        if (quarter == 0) {
            float inv  = (d > 0.f) ? (1.f / d) : 0.f;
            float bgat = (d > 0.f) ? 1.f : 0.f;
            float4 ska = *(const float4*)(g_S + (size_t)n * 64 + coff);
            float4 skb = *(const float4*)(g_S + (size_t)n * 64 + coff + 4);
            float4 bea = *(const float4*)(be_l + coff);
            float4 beb = *(const float4*)(be_l + coff + 4);
            float sk[8] = {ska.x, ska.y, ska.z, ska.w, skb.x, skb.y, skb.z, skb.w};
            float be8[8] = {bea.x, bea.y, bea.z, bea.w, beb.x, beb.y, beb.z, beb.w};
            float o[8];
#pragma unroll
            for (int j = 0; j < 8; j++) {
                float v = (acc[j] + ws[j]) * inv + bgat * be8[j] + sk[j];
                o[j] = do_relu ? fmaxf(v, 0.f) : v;
            }
            *(float4*)(Hout + (size_t)n * 64 + coff)     = make_float4(o[0], o[1], o[2], o[3]);
            *(float4*)(Hout + (size_t)n * 64 + coff + 4) = make_float4(o[4], o[5], o[6], o[7]);
        }
    }
}

// ---------------- mean pool ----------------
__global__ void k_pool(const int* __restrict__ batch) {
    int idx = blockIdx.x * blockDim.x + threadIdx.x;
    if (idx < N_NODES * 64) {
        int n = idx >> 6, c = idx & 63;
        int g = batch[n];
        if (g >= 0 && g < NGRAPHS) {
            atomicAdd(&g_pool[g * 64 + c], g_H0[idx]);
            if (c == 0) atomicAdd(&g_gcnt[g], 1.f);
        }
    }
}

// ---------------- head MLP ----------------
__global__ void k_final(const float* __restrict__ l1w, const float* __restrict__ l1b,
                        const float* __restrict__ l2w, const float* __restrict__ l2b,
                        float* __restrict__ out) {
    __shared__ float w1[4096];
    __shared__ float b1[64];
    __shared__ float w2[64];
    int t = threadIdx.x;
    for (int i = t; i < 4096; i += 128) w1[i] = l1w[i];
    if (t < 64) { b1[t] = l1b[t]; w2[t] = l2w[t]; }
    __syncthreads();
    if (t < NGRAPHS) {
        float inv = 1.f / fmaxf(g_gcnt[t], 1.f);
        float p[64];
#pragma unroll
        for (int c = 0; c < 64; c++) p[c] = g_pool[t * 64 + c] * inv;
        float o = l2b[0];
        for (int oc = 0; oc < 64; oc++) {
            float h = b1[oc];
#pragma unroll
            for (int i = 0; i < 64; i++) h = fmaf(p[i], w1[i * 64 + oc], h);
            o = fmaf(fmaxf(h, 0.f), w2[oc], o);
        }
        out[t] = o;
    }
}

// ---------------- trailing cleanup ----------------
__global__ void k_cleanup() {
    int i = blockIdx.x * blockDim.x + threadIdx.x;
    if (i < N_NODES) g_cnt[i] = 0;
    if (i < NGRAPHS * 64) g_pool[i] = 0.f;
    if (i < NGRAPHS) g_gcnt[i] = 0.f;
}

// ---------------- launch ----------------
extern "C" void kernel_launch(void* const* d_in, const int* in_sizes, int n_in,
                              void* d_out, int out_size) {
    const float* x     = (const float*)d_in[0];
    const int*   ei    = (const int*)d_in[1];
    const float* eattr = (const float*)d_in[2];
    const int*   batch = (const int*)d_in[3];
    const float* Wq = (const float*)d_in[4];
    const float* bq = (const float*)d_in[5];
    const float* Wk = (const float*)d_in[6];
    const float* bk = (const float*)d_in[7];
    const float* Wv = (const float*)d_in[8];
    const float* bv = (const float*)d_in[9];
    const float* We = (const float*)d_in[10];
    const float* be = (const float*)d_in[11];
    const float* Ws = (const float*)d_in[12];
    const float* bs = (const float*)d_in[13];
    const float* l1w = (const float*)d_in[14];
    const float* l1b = (const float*)d_in[15];
    const float* l2w = (const float*)d_in[16];
    const float* l2b = (const float*)d_in[17];
    float* out = (float*)d_out;

    k_hist<<<(N_EDGES + 255) / 256, 256>>>(ei);
    k_scan<<<1, 1024>>>();
    k_scatter<<<(N_EDGES + 255) / 256, 256>>>(ei, eattr);

    dim3 gemm_grid((N_NODES + 63) / 64, 4);
    const int qe_blocks = (N_NODES * 64 + 255) / 256;
    const int edge_blocks = 2048;

    // layer 0
    k_qkvs<<<gemm_grid, 128>>>(0, x, Wq, Wk, Wv, Ws, bq, bk, bv, bs);
    k_qe<<<qe_blocks, 256>>>(We);
    k_edge<<<edge_blocks, 256>>>(We, be, 0, 1);
    // layer 1
    k_qkvs<<<gemm_grid, 128>>>(1, x, Wq + 4096, Wk + 4096, Wv + 4096, Ws + 4096,
                               bq + 64, bk + 64, bv + 64, bs + 64);
    k_qe<<<qe_blocks, 256>>>(We + 1024);
    k_edge<<<edge_blocks, 256>>>(We + 1024, be + 64, 1, 1);
    // layer 2
    k_qkvs<<<gemm_grid, 128>>>(2, x, Wq + 8192, Wk + 8192, Wv + 8192, Ws + 8192,
                               bq + 128, bk + 128, bv + 128, bs + 128);
    k_qe<<<qe_blocks, 256>>>(We + 2048);
    k_edge<<<edge_blocks, 256>>>(We + 2048, be + 128, 0, 0);

    k_pool<<<(N_NODES * 64 + 255) / 256, 256>>>(batch);
    k_final<<<1, 128>>>(l1w, l1b, l2w, l2b, out);
    k_cleanup<<<(N_NODES + 255) / 256, 256>>>();
}

// round 10
// speedup vs baseline: 1.2649x; 1.2649x over previous
#include <cuda_runtime.h>
#include <cuda_fp16.h>
#include <math_constants.h>

#define N_NODES   100000
#define N_EDGES   1200000
#define NGRAPHS   128

// ---------------- scratch (device globals: allocation-free) ----------------
__device__ float  g_Q[N_NODES * 64];
__device__ float  g_QE[N_NODES * 64];
__device__ __half g_KV[N_NODES * 128];   // K halves [0,64), V halves [64,128)
__device__ float  g_S[N_NODES * 64];
__device__ float  g_H0[N_NODES * 64];
__device__ float  g_H1[N_NODES * 64];
__device__ __half g_pattr[(size_t)N_EDGES * 16];  // edge_attr, CSR order, fp16
__device__ int    g_cnt[N_NODES];        // zeroed at load; re-zeroed by k_cleanup
__device__ int    g_rowptr[N_NODES + 1];
__device__ int    g_cursor[N_NODES];
__device__ int    g_psrc[N_EDGES];
__device__ float  g_pool[NGRAPHS * 64];
__device__ float  g_gcnt[NGRAPHS];

__device__ __forceinline__ float ex2(float x) {
    float y;
    asm("ex2.approx.ftz.f32 %0, %1;" : "=f"(y) : "f"(x));
    return y;
}
__device__ __forceinline__ void ldsm_x4(unsigned* r, unsigned addr) {
    asm volatile("ldmatrix.sync.aligned.m8n8.x4.shared.b16 {%0,%1,%2,%3}, [%4];"
                 : "=r"(r[0]), "=r"(r[1]), "=r"(r[2]), "=r"(r[3]) : "r"(addr));
}
__device__ __forceinline__ void ldsm_x2t(unsigned* r, unsigned addr) {
    asm volatile("ldmatrix.sync.aligned.m8n8.x2.trans.shared.b16 {%0,%1}, [%2];"
                 : "=r"(r[0]), "=r"(r[1]) : "r"(addr));
}
__device__ __forceinline__ void mma16816(float* c, const unsigned* a, const unsigned* b) {
    asm volatile("mma.sync.aligned.m16n8k16.row.col.f32.f16.f16.f32 "
                 "{%0,%1,%2,%3}, {%4,%5,%6,%7}, {%8,%9}, {%0,%1,%2,%3};"
                 : "+f"(c[0]), "+f"(c[1]), "+f"(c[2]), "+f"(c[3])
                 : "r"(a[0]), "r"(a[1]), "r"(a[2]), "r"(a[3]), "r"(b[0]), "r"(b[1]));
}
// hi/lo split: v = hi + lo to ~2^-22
__device__ __forceinline__ void split2(float2 v, __half2& hi, __half2& lo) {
    hi = __float22half2_rn(v);
    float2 h = __half22float2(hi);
    lo = __float22half2_rn(make_float2(v.x - h.x, v.y - h.y));
}

// ---------------- CSR build ----------------
__global__ void k_hist(const int* __restrict__ ei) {
    int e = blockIdx.x * blockDim.x + threadIdx.x;
    if (e < N_EDGES) {
        int d = ei[N_EDGES + e];
        if (d >= 0 && d < N_NODES) atomicAdd(&g_cnt[d], 1);
    }
}

__global__ void k_scan() {
    __shared__ int part[1024];
    const int CH = 98;
    int t = threadIdx.x;
    int beg = t * CH;
    int end = beg + CH; if (end > N_NODES) end = N_NODES;
    int s = 0;
    for (int i = beg; i < end; i++) s += g_cnt[i];
    part[t] = s;
    __syncthreads();
    for (int off = 1; off < 1024; off <<= 1) {
        int v = (t >= off) ? part[t - off] : 0;
        __syncthreads();
        part[t] += v;
        __syncthreads();
    }
    int run = (t > 0) ? part[t - 1] : 0;
    for (int i = beg; i < end; i++) {
        g_rowptr[i] = run;
        g_cursor[i] = run;
        run += g_cnt[i];
    }
    if (t == 0) g_rowptr[N_NODES] = part[1023];
}

// scatter src + convert/permute edge_attr to fp16 CSR order, in one pass
__global__ void k_scatter(const int* __restrict__ ei, const float* __restrict__ eattr) {
    int e = blockIdx.x * blockDim.x + threadIdx.x;
    if (e < N_EDGES) {
        int d = ei[N_EDGES + e];
        if (d >= 0 && d < N_NODES) {
            int p = atomicAdd(&g_cursor[d], 1);
            g_psrc[p] = ei[e];
            const float4* ap = (const float4*)(eattr + (size_t)e * 16);
            float4 a0 = __ldg(ap + 0), a1 = __ldg(ap + 1);
            float4 a2 = __ldg(ap + 2), a3 = __ldg(ap + 3);
            __half2 h[8];
            h[0] = __float22half2_rn(make_float2(a0.x, a0.y));
            h[1] = __float22half2_rn(make_float2(a0.z, a0.w));
            h[2] = __float22half2_rn(make_float2(a1.x, a1.y));
            h[3] = __float22half2_rn(make_float2(a1.z, a1.w));
            h[4] = __float22half2_rn(make_float2(a2.x, a2.y));
            h[5] = __float22half2_rn(make_float2(a2.z, a2.w));
            h[6] = __float22half2_rn(make_float2(a3.x, a3.y));
            h[7] = __float22half2_rn(make_float2(a3.z, a3.w));
            uint4* dst = (uint4*)(g_pattr + (size_t)p * 16);
            dst[0] = *(uint4*)&h[0];
            dst[1] = *(uint4*)&h[4];
        }
    }
}

// ---------------- QKVS GEMM via split-fp16 HMMA (Markidis 3-term) ----------
#define XST 72
__global__ void __launch_bounds__(128)
k_qkvs(int insel, const float* __restrict__ Xext,
       const float* __restrict__ Wq, const float* __restrict__ Wk,
       const float* __restrict__ Wv, const float* __restrict__ Ws,
       const float* __restrict__ bq, const float* __restrict__ bk,
       const float* __restrict__ bv, const float* __restrict__ bs) {
    __shared__ __half Xhi[64 * XST], Xlo[64 * XST];
    __shared__ __half Whi[64 * XST], Wlo[64 * XST];

    const float* X = (insel == 0) ? Xext : (insel == 1) ? g_H0 : g_H1;
    int mat = blockIdx.y;
    const float* W = (mat == 0) ? Wq : (mat == 1) ? Wk : (mat == 2) ? Wv : Ws;
    const float* b = (mat == 0) ? bq : (mat == 1) ? bk : (mat == 2) ? bv : bs;

    int tid = threadIdx.x;
    int warp = tid >> 5, lane = tid & 31;
    int rowBase = blockIdx.x * 64;

    for (int i = tid; i < 1024; i += 128) {
        int r = i >> 4, c4 = (i & 15) * 4;
        int row = rowBase + r;
        float4 v = (row < N_NODES) ? *(const float4*)(X + (size_t)row * 64 + c4)
                                   : make_float4(0.f, 0.f, 0.f, 0.f);
        __half2 hi, lo;
        split2(make_float2(v.x, v.y), hi, lo);
        *(__half2*)(Xhi + r * XST + c4) = hi;
        *(__half2*)(Xlo + r * XST + c4) = lo;
        split2(make_float2(v.z, v.w), hi, lo);
        *(__half2*)(Xhi + r * XST + c4 + 2) = hi;
        *(__half2*)(Xlo + r * XST + c4 + 2) = lo;

        float4 w = *(const float4*)(W + r * 64 + c4);
        split2(make_float2(w.x, w.y), hi, lo);
        *(__half2*)(Whi + r * XST + c4) = hi;
        *(__half2*)(Wlo + r * XST + c4) = lo;
        split2(make_float2(w.z, w.w), hi, lo);
        *(__half2*)(Whi + r * XST + c4 + 2) = hi;
        *(__half2*)(Wlo + r * XST + c4 + 2) = lo;
    }
    __syncthreads();

    unsigned xhi_a = (unsigned)__cvta_generic_to_shared(Xhi);
    unsigned xlo_a = (unsigned)__cvta_generic_to_shared(Xlo);
    unsigned whi_a = (unsigned)__cvta_generic_to_shared(Whi);
    unsigned wlo_a = (unsigned)__cvta_generic_to_shared(Wlo);
    int warpRow = warp * 16;
    int lr = lane & 15, lh = lane >> 4;

    float acc[8][4];
#pragma unroll
    for (int nb = 0; nb < 8; nb++)
#pragma unroll
        for (int j = 0; j < 4; j++) acc[nb][j] = 0.f;

#pragma unroll
    for (int ks = 0; ks < 4; ks++) {
        unsigned ahi[4], alo[4];
        unsigned aoff = ((warpRow + lr) * XST + ks * 16 + lh * 8) * 2;
        ldsm_x4(ahi, xhi_a + aoff);
        ldsm_x4(alo, xlo_a + aoff);
#pragma unroll
        for (int nb = 0; nb < 8; nb++) {
            unsigned bhi[2], blo[2];
            unsigned boff = ((ks * 16 + lr) * XST + nb * 8) * 2;
            ldsm_x2t(bhi, whi_a + boff);
            ldsm_x2t(blo, wlo_a + boff);
            mma16816(acc[nb], ahi, bhi);
            mma16816(acc[nb], ahi, blo);
            mma16816(acc[nb], alo, bhi);
        }
    }

    int r0 = rowBase + warpRow + (lane >> 2);
    int cb = 2 * (lane & 3);
    if (mat == 0 || mat == 3) {
        float* out = (mat == 0) ? g_Q : g_S;
#pragma unroll
        for (int nb = 0; nb < 8; nb++) {
            int col = nb * 8 + cb;
            float2 bv = *(const float2*)(b + col);
            if (r0 < N_NODES)
                *(float2*)(out + (size_t)r0 * 64 + col) =
                    make_float2(acc[nb][0] + bv.x, acc[nb][1] + bv.y);
            if (r0 + 8 < N_NODES)
                *(float2*)(out + (size_t)(r0 + 8) * 64 + col) =
                    make_float2(acc[nb][2] + bv.x, acc[nb][3] + bv.y);
        }
    } else {
        int off = (mat == 1) ? 0 : 64;
#pragma unroll
        for (int nb = 0; nb < 8; nb++) {
            int col = nb * 8 + cb;
            float2 bv = *(const float2*)(b + col);
            if (r0 < N_NODES)
                *(__half2*)(g_KV + (size_t)r0 * 128 + off + col) =
                    __float22half2_rn(make_float2(acc[nb][0] + bv.x, acc[nb][1] + bv.y));
            if (r0 + 8 < N_NODES)
                *(__half2*)(g_KV + (size_t)(r0 + 8) * 128 + off + col) =
                    __float22half2_rn(make_float2(acc[nb][2] + bv.x, acc[nb][3] + bv.y));
        }
    }
}

// ---------------- qe precompute: qe[n,h*16+j] = QS * sum_d Q[n,h,d]*We[j,h,d]
__global__ void k_qe(const float* __restrict__ We_l) {
    __shared__ float Wsm[16 * 68];
    int tid = threadIdx.x;
    for (int i = tid; i < 1024; i += 256)
        Wsm[(i >> 6) * 68 + (i & 63)] = We_l[i];
    __syncthreads();
    const float QS = 0.25f * 1.4426950408889634f;   // 1/sqrt(16) * log2(e)
    int idx = blockIdx.x * 256 + tid;
    if (idx < N_NODES * 64) {
        int n = idx >> 6, p = idx & 63;
        int h = p >> 4, j = p & 15;
        const float* qrow = g_Q + n * 64 + h * 16;
        const float* wrow = Wsm + j * 68 + h * 16;
        float s = 0.f;
#pragma unroll
        for (int d = 0; d < 16; d++) s = fmaf(qrow[d], wrow[d], s);
        g_QE[idx] = s * QS;
    }
}

// ---------------- edge attention: warp per dst node, fp16 gathers, unroll 4
__global__ void __launch_bounds__(256) k_edge(const float* __restrict__ We_l,
                                              const float* __restrict__ be_l,
                                              int outsel, int do_relu) {
    __shared__ float sWe[1024];
    float* Hout = (outsel == 0) ? g_H0 : g_H1;
    int tid = threadIdx.x;
    for (int i = tid; i < 1024; i += 256) sWe[i] = We_l[i];
    __syncthreads();

    int lane = tid & 31;
    int gw = (blockIdx.x * 256 + tid) >> 5;
    int nw = (gridDim.x * 256) >> 5;

    const float QS = 0.25f * 1.4426950408889634f;
    int ai = lane & 7;              // this lane's half2 index in the attr row
    int base = lane & 24;           // first lane of this head's 8-lane group
    float2 be2 = *(const float2*)(be_l + 2 * lane);

    for (int n = gw; n < N_NODES; n += nw) {
        int beg = g_rowptr[n], end = g_rowptr[n + 1];
        float2 q  = *(const float2*)(g_Q  + n * 64 + 2 * lane);
        float2 qe = *(const float2*)(g_QE + n * 64 + 2 * lane);
        q.x *= QS; q.y *= QS;

        float m = -CUDART_INF_F;
        float d = 0.f;
        float2 acc = make_float2(0.f, 0.f);
        float2 t   = make_float2(0.f, 0.f);

        int e = beg;
        for (; e + 3 < end; e += 4) {
            int s0 = g_psrc[e],     s1 = g_psrc[e + 1];
            int s2 = g_psrc[e + 2], s3 = g_psrc[e + 3];
            const __half2* kr0 = (const __half2*)(g_KV + (size_t)s0 * 128);
            const __half2* kr1 = (const __half2*)(g_KV + (size_t)s1 * 128);
            const __half2* kr2 = (const __half2*)(g_KV + (size_t)s2 * 128);
            const __half2* kr3 = (const __half2*)(g_KV + (size_t)s3 * 128);
            float2 a0 = __half22float2(((const __half2*)(g_pattr + (size_t)e * 16))[ai]);
            float2 a1 = __half22float2(((const __half2*)(g_pattr + (size_t)(e + 1) * 16))[ai]);
            float2 a2 = __half22float2(((const __half2*)(g_pattr + (size_t)(e + 2) * 16))[ai]);
            float2 a3 = __half22float2(((const __half2*)(g_pattr + (size_t)(e + 3) * 16))[ai]);
            float2 k0 = __half22float2(kr0[lane]);
            float2 v0 = __half22float2(kr0[32 + lane]);
            float2 k1 = __half22float2(kr1[lane]);
            float2 v1 = __half22float2(kr1[32 + lane]);
            float2 k2 = __half22float2(kr2[lane]);
            float2 v2 = __half22float2(kr2[32 + lane]);
            float2 k3 = __half22float2(kr3[lane]);
            float2 v3 = __half22float2(kr3[32 + lane]);

            float lp0 = q.x * k0.x, lp1 = q.x * k1.x;
            float lp2 = q.x * k2.x, lp3 = q.x * k3.x;
            lp0 = fmaf(q.y,  k0.y, lp0);  lp1 = fmaf(q.y,  k1.y, lp1);
            lp2 = fmaf(q.y,  k2.y, lp2);  lp3 = fmaf(q.y,  k3.y, lp3);
            lp0 = fmaf(qe.x, a0.x, lp0);  lp1 = fmaf(qe.x, a1.x, lp1);
            lp2 = fmaf(qe.x, a2.x, lp2);  lp3 = fmaf(qe.x, a3.x, lp3);
            lp0 = fmaf(qe.y, a0.y, lp0);  lp1 = fmaf(qe.y, a1.y, lp1);
            lp2 = fmaf(qe.y, a2.y, lp2);  lp3 = fmaf(qe.y, a3.y, lp3);
            lp0 += __shfl_xor_sync(0xffffffffu, lp0, 1);
            lp1 += __shfl_xor_sync(0xffffffffu, lp1, 1);
            lp2 += __shfl_xor_sync(0xffffffffu, lp2, 1);
            lp3 += __shfl_xor_sync(0xffffffffu, lp3, 1);
            lp0 += __shfl_xor_sync(0xffffffffu, lp0, 2);
            lp1 += __shfl_xor_sync(0xffffffffu, lp1, 2);
            lp2 += __shfl_xor_sync(0xffffffffu, lp2, 2);
            lp3 += __shfl_xor_sync(0xffffffffu, lp3, 2);
            lp0 += __shfl_xor_sync(0xffffffffu, lp0, 4);
            lp1 += __shfl_xor_sync(0xffffffffu, lp1, 4);
            lp2 += __shfl_xor_sync(0xffffffffu, lp2, 4);
            lp3 += __shfl_xor_sync(0xffffffffu, lp3, 4);

            float mx01 = fmaxf(lp0, lp1), mx23 = fmaxf(lp2, lp3);
            float nm = fmaxf(m, fmaxf(mx01, mx23));
            float p0 = ex2(lp0 - nm);
            float p1 = ex2(lp1 - nm);
            float p2 = ex2(lp2 - nm);
            float p3 = ex2(lp3 - nm);
            float sc = ex2(m - nm);
            d = fmaf(d, sc, (p0 + p1) + (p2 + p3));
            acc.x = fmaf(acc.x, sc,
                         fmaf(p0, v0.x, fmaf(p1, v1.x, fmaf(p2, v2.x, p3 * v3.x))));
            acc.y = fmaf(acc.y, sc,
                         fmaf(p0, v0.y, fmaf(p1, v1.y, fmaf(p2, v2.y, p3 * v3.y))));
            t.x   = fmaf(t.x, sc,
                         fmaf(p0, a0.x, fmaf(p1, a1.x, fmaf(p2, a2.x, p3 * a3.x))));
            t.y   = fmaf(t.y, sc,
                         fmaf(p0, a0.y, fmaf(p1, a1.y, fmaf(p2, a2.y, p3 * a3.y))));
            m = nm;
        }
        for (; e < end; e++) {
            int s0 = g_psrc[e];
            const __half2* kr0 = (const __half2*)(g_KV + (size_t)s0 * 128);
            float2 a0 = __half22float2(((const __half2*)(g_pattr + (size_t)e * 16))[ai]);
            float2 k0 = __half22float2(kr0[lane]);
            float2 v0 = __half22float2(kr0[32 + lane]);
            float lp0 = q.x * k0.x;
            lp0 = fmaf(q.y,  k0.y, lp0);
            lp0 = fmaf(qe.x, a0.x, lp0);
            lp0 = fmaf(qe.y, a0.y, lp0);
            lp0 += __shfl_xor_sync(0xffffffffu, lp0, 1);
            lp0 += __shfl_xor_sync(0xffffffffu, lp0, 2);
            lp0 += __shfl_xor_sync(0xffffffffu, lp0, 4);
            float nm = fmaxf(m, lp0);
            float p0 = ex2(lp0 - nm);
            float sc = ex2(m - nm);
            d = fmaf(d, sc, p0);
            acc.x = fmaf(acc.x, sc, p0 * v0.x);
            acc.y = fmaf(acc.y, sc, p0 * v0.y);
            t.x   = fmaf(t.x,   sc, p0 * a0.x);
            t.y   = fmaf(t.y,   sc, p0 * a0.y);
            m = nm;
        }

        // epilogue: out = (acc + We^T t)/d + [deg>0]*be + skip
        float2 ws = make_float2(0.f, 0.f);
#pragma unroll
        for (int j2 = 0; j2 < 8; j2++) {
            float tx_ = __shfl_sync(0xffffffffu, t.x, base + j2);
            float ty_ = __shfl_sync(0xffffffffu, t.y, base + j2);
            float2 w0 = *(const float2*)(sWe + (2 * j2) * 64 + 2 * lane);
            float2 w1 = *(const float2*)(sWe + (2 * j2 + 1) * 64 + 2 * lane);
            ws.x = fmaf(w0.x, tx_, ws.x);
            ws.y = fmaf(w0.y, tx_, ws.y);
            ws.x = fmaf(w1.x, ty_, ws.x);
            ws.y = fmaf(w1.y, ty_, ws.y);
        }

        float2 sk = *(const float2*)(g_S + n * 64 + 2 * lane);
        float inv  = (d > 0.f) ? (1.f / d) : 0.f;
        float bgat = (d > 0.f) ? 1.f : 0.f;
        float ox = (acc.x + ws.x) * inv + bgat * be2.x + sk.x;
        float oy = (acc.y + ws.y) * inv + bgat * be2.y + sk.y;
        if (do_relu) { ox = fmaxf(ox, 0.f); oy = fmaxf(oy, 0.f); }
        *(float2*)(Hout + n * 64 + 2 * lane) = make_float2(ox, oy);
    }
}

// ---------------- mean pool ----------------
__global__ void k_pool(const int* __restrict__ batch) {
    int idx = blockIdx.x * blockDim.x + threadIdx.x;
    if (idx < N_NODES * 64) {
        int n = idx >> 6, c = idx & 63;
        int g = batch[n];
        if (g >= 0 && g < NGRAPHS) {
            atomicAdd(&g_pool[g * 64 + c], g_H0[idx]);
            if (c == 0) atomicAdd(&g_gcnt[g], 1.f);
        }
    }
}

// ---------------- head MLP ----------------
__global__ void k_final(const float* __restrict__ l1w, const float* __restrict__ l1b,
                        const float* __restrict__ l2w, const float* __restrict__ l2b,
                        float* __restrict__ out) {
    __shared__ float w1[4096];
    __shared__ float b1[64];
    __shared__ float w2[64];
    int t = threadIdx.x;
    for (int i = t; i < 4096; i += 128) w1[i] = l1w[i];
    if (t < 64) { b1[t] = l1b[t]; w2[t] = l2w[t]; }
    __syncthreads();
    if (t < NGRAPHS) {
        float inv = 1.f / fmaxf(g_gcnt[t], 1.f);
        float p[64];
#pragma unroll
        for (int c = 0; c < 64; c++) p[c] = g_pool[t * 64 + c] * inv;
        float o = l2b[0];
        for (int oc = 0; oc < 64; oc++) {
            float h = b1[oc];
#pragma unroll
            for (int i = 0; i < 64; i++) h = fmaf(p[i], w1[i * 64 + oc], h);
            o = fmaf(fmaxf(h, 0.f), w2[oc], o);
        }
        out[t] = o;
    }
}

// ---------------- trailing cleanup ----------------
__global__ void k_cleanup() {
    int i = blockIdx.x * blockDim.x + threadIdx.x;
    if (i < N_NODES) g_cnt[i] = 0;
    if (i < NGRAPHS * 64) g_pool[i] = 0.f;
    if (i < NGRAPHS) g_gcnt[i] = 0.f;
}

// ---------------- launch ----------------
extern "C" void kernel_launch(void* const* d_in, const int* in_sizes, int n_in,
                              void* d_out, int out_size) {
    const float* x     = (const float*)d_in[0];
    const int*   ei    = (const int*)d_in[1];
    const float* eattr = (const float*)d_in[2];
    const int*   batch = (const int*)d_in[3];
    const float* Wq = (const float*)d_in[4];
    const float* bq = (const float*)d_in[5];
    const float* Wk = (const float*)d_in[6];
    const float* bk = (const float*)d_in[7];
    const float* Wv = (const float*)d_in[8];
    const float* bv = (const float*)d_in[9];
    const float* We = (const float*)d_in[10];
    const float* be = (const float*)d_in[11];
    const float* Ws = (const float*)d_in[12];
    const float* bs = (const float*)d_in[13];
    const float* l1w = (const float*)d_in[14];
    const float* l1b = (const float*)d_in[15];
    const float* l2w = (const float*)d_in[16];
    const float* l2b = (const float*)d_in[17];
    float* out = (float*)d_out;

    k_hist<<<(N_EDGES + 255) / 256, 256>>>(ei);
    k_scan<<<1, 1024>>>();
    k_scatter<<<(N_EDGES + 255) / 256, 256>>>(ei, eattr);

    dim3 gemm_grid((N_NODES + 63) / 64, 4);
    const int qe_blocks = (N_NODES * 64 + 255) / 256;
    const int edge_blocks = 2048;

    // layer 0
    k_qkvs<<<gemm_grid, 128>>>(0, x, Wq, Wk, Wv, Ws, bq, bk, bv, bs);
    k_qe<<<qe_blocks, 256>>>(We);
    k_edge<<<edge_blocks, 256>>>(We, be, 0, 1);
    // layer 1
    k_qkvs<<<gemm_grid, 128>>>(1, x, Wq + 4096, Wk + 4096, Wv + 4096, Ws + 4096,
                               bq + 64, bk + 64, bv + 64, bs + 64);
    k_qe<<<qe_blocks, 256>>>(We + 1024);
    k_edge<<<edge_blocks, 256>>>(We + 1024, be + 64, 1, 1);
    // layer 2
    k_qkvs<<<gemm_grid, 128>>>(2, x, Wq + 8192, Wk + 8192, Wv + 8192, Ws + 8192,
                               bq + 128, bk + 128, bv + 128, bs + 128);
    k_qe<<<qe_blocks, 256>>>(We + 2048);
    k_edge<<<edge_blocks, 256>>>(We + 2048, be + 128, 0, 0);

    k_pool<<<(N_NODES * 64 + 255) / 256, 256>>>(batch);
    k_final<<<1, 128>>>(l1w, l1b, l2w, l2b, out);
    k_cleanup<<<(N_NODES + 255) / 256, 256>>>();
}